// round 1
// baseline (speedup 1.0000x reference)
#include <cuda_runtime.h>
#include <cstdint>

#define DM   512
#define LSEQ 2048
#define BSZ  8
#define MTOT (BSZ * LSEQ)      /* 16384 rows */
#define NCH  8
#define CHUNK (LSEQ / NCH)     /* 256 */

// Scratch (allocation-free: __device__ globals)
__device__ float g_h[(size_t)MTOT * DM];            // 33.5 MB: post-GEMM / post-LN activations
__device__ float g_csum[BSZ * NCH * DM];            // per-chunk sums of h
__device__ float g_Sre[BSZ * DM];                   // S = sum_{t<256} A^t h[t]
__device__ float g_Sim[BSZ * DM];

// ---------------------------------------------------------------------------
// Kernel 1: H[m][n] = sum_k X[m][k] * W[n][k] + bias[n]
// Classic 128x128x8 double-buffered SGEMM, 256 threads, 8x8 per thread.
// ---------------------------------------------------------------------------
__global__ __launch_bounds__(256, 2)
void gemm_bias_kernel(const float* __restrict__ X, const float* __restrict__ W,
                      const float* __restrict__ bias)
{
    __shared__ float As[2][8][132];
    __shared__ float Bs[2][8][132];

    const int tid  = threadIdx.x;
    const int bm   = blockIdx.y * 128;
    const int bn   = blockIdx.x * 128;
    const int tx   = tid & 15;        // 0..15  (n direction)
    const int ty   = tid >> 4;        // 0..15  (m direction)
    const int lrow = tid >> 1;        // 0..127
    const int lk4  = (tid & 1) * 4;   // 0 or 4

    const float* Xp = X + (size_t)(bm + lrow) * DM + lk4;
    const float* Wp = W + (size_t)(bn + lrow) * DM + lk4;

    // preload first K-tile into buffer 0
    {
        float4 xa = *(const float4*)(Xp);
        float4 wa = *(const float4*)(Wp);
        As[0][lk4 + 0][lrow] = xa.x; As[0][lk4 + 1][lrow] = xa.y;
        As[0][lk4 + 2][lrow] = xa.z; As[0][lk4 + 3][lrow] = xa.w;
        Bs[0][lk4 + 0][lrow] = wa.x; Bs[0][lk4 + 1][lrow] = wa.y;
        Bs[0][lk4 + 2][lrow] = wa.z; Bs[0][lk4 + 3][lrow] = wa.w;
    }
    __syncthreads();

    float acc[8][8];
#pragma unroll
    for (int i = 0; i < 8; ++i)
#pragma unroll
        for (int j = 0; j < 8; ++j) acc[i][j] = 0.0f;

    const int nkt = DM / 8;   // 64
    int buf = 0;
    for (int kt = 0; kt < nkt; ++kt) {
        float4 xn, wn;
        const bool has_next = (kt + 1) < nkt;
        if (has_next) {
            xn = *(const float4*)(Xp + (size_t)(kt + 1) * 8);
            wn = *(const float4*)(Wp + (size_t)(kt + 1) * 8);
        }
#pragma unroll
        for (int k = 0; k < 8; ++k) {
            float a[8], b[8];
            *(float4*)&a[0] = *(const float4*)&As[buf][k][ty * 8 + 0];
            *(float4*)&a[4] = *(const float4*)&As[buf][k][ty * 8 + 4];
            *(float4*)&b[0] = *(const float4*)&Bs[buf][k][tx * 8 + 0];
            *(float4*)&b[4] = *(const float4*)&Bs[buf][k][tx * 8 + 4];
#pragma unroll
            for (int i = 0; i < 8; ++i)
#pragma unroll
                for (int j = 0; j < 8; ++j)
                    acc[i][j] = fmaf(a[i], b[j], acc[i][j]);
        }
        if (has_next) {
            const int nb = buf ^ 1;
            As[nb][lk4 + 0][lrow] = xn.x; As[nb][lk4 + 1][lrow] = xn.y;
            As[nb][lk4 + 2][lrow] = xn.z; As[nb][lk4 + 3][lrow] = xn.w;
            Bs[nb][lk4 + 0][lrow] = wn.x; Bs[nb][lk4 + 1][lrow] = wn.y;
            Bs[nb][lk4 + 2][lrow] = wn.z; Bs[nb][lk4 + 3][lrow] = wn.w;
            __syncthreads();
            buf = nb;
        }
    }

    // epilogue: +bias, store to g_h
    float bv[8];
#pragma unroll
    for (int j = 0; j < 8; ++j) bv[j] = bias[bn + tx * 8 + j];
#pragma unroll
    for (int i = 0; i < 8; ++i) {
        float* Hp = g_h + (size_t)(bm + ty * 8 + i) * DM + bn + tx * 8;
        float4 v0, v1;
        v0.x = acc[i][0] + bv[0]; v0.y = acc[i][1] + bv[1];
        v0.z = acc[i][2] + bv[2]; v0.w = acc[i][3] + bv[3];
        v1.x = acc[i][4] + bv[4]; v1.y = acc[i][5] + bv[5];
        v1.z = acc[i][6] + bv[6]; v1.w = acc[i][7] + bv[7];
        *(float4*)(Hp + 0) = v0;
        *(float4*)(Hp + 4) = v1;
    }
}

// ---------------------------------------------------------------------------
// Kernel 2: LayerNorm over the feature dim, in place on g_h.
// One warp per row (512 floats). grid = 2048 blocks x 256 threads (8 warps).
// ---------------------------------------------------------------------------
__global__ __launch_bounds__(256)
void ln_kernel(const float* __restrict__ gamma, const float* __restrict__ beta)
{
    const int warp = threadIdx.x >> 5;
    const int lane = threadIdx.x & 31;
    const int row  = blockIdx.x * 8 + warp;   // < 16384

    float* p = g_h + (size_t)row * DM;
    float4 v[4];
    float s = 0.0f, s2 = 0.0f;
#pragma unroll
    for (int i = 0; i < 4; ++i) {
        v[i] = *(const float4*)(p + lane * 4 + i * 128);
        s  += v[i].x + v[i].y + v[i].z + v[i].w;
        s2 += v[i].x * v[i].x + v[i].y * v[i].y + v[i].z * v[i].z + v[i].w * v[i].w;
    }
#pragma unroll
    for (int o = 16; o > 0; o >>= 1) {
        s  += __shfl_xor_sync(0xFFFFFFFFu, s,  o);
        s2 += __shfl_xor_sync(0xFFFFFFFFu, s2, o);
    }
    const float mu   = s * (1.0f / DM);
    const float var  = s2 * (1.0f / DM) - mu * mu;
    const float rstd = rsqrtf(var + 1e-5f);
#pragma unroll
    for (int i = 0; i < 4; ++i) {
        const int c0 = lane * 4 + i * 128;
        float4 g = *(const float4*)(gamma + c0);
        float4 bt = *(const float4*)(beta + c0);
        float4 o;
        o.x = (v[i].x - mu) * rstd * g.x + bt.x;
        o.y = (v[i].y - mu) * rstd * g.y + bt.y;
        o.z = (v[i].z - mu) * rstd * g.z + bt.z;
        o.w = (v[i].w - mu) * rstd * g.w + bt.w;
        *(float4*)(p + c0) = o;
    }
}

// ---------------------------------------------------------------------------
// Kernel 3: per-chunk sums of h over l, and (for chunk 0) the complex
// windowed sum S = sum_{t=0..255} A^t h[t]   (A^t underflows to 0 by t~100).
// grid = (NCH, BSZ), 512 threads (one per channel d).
// ---------------------------------------------------------------------------
__global__ __launch_bounds__(512)
void pass1_kernel(const float* __restrict__ Are, const float* __restrict__ Aim)
{
    const int d = threadIdx.x;
    const int c = blockIdx.x;
    const int b = blockIdx.y;
    const float* p = g_h + ((size_t)b * LSEQ + (size_t)c * CHUNK) * DM + d;

    float s0 = 0.f, s1 = 0.f, s2 = 0.f, s3 = 0.f;
#pragma unroll 4
    for (int i = 0; i < CHUNK; i += 4) {
        s0 += p[(size_t)(i + 0) * DM];
        s1 += p[(size_t)(i + 1) * DM];
        s2 += p[(size_t)(i + 2) * DM];
        s3 += p[(size_t)(i + 3) * DM];
    }
    g_csum[(b * NCH + c) * DM + d] = (s0 + s1) + (s2 + s3);

    if (c == 0) {
        const float are = Are[d], aim = Aim[d];
        float pre = 1.0f, pim = 0.0f, Sre = 0.0f, Sim = 0.0f;
        for (int i = 0; i < CHUNK; ++i) {
            const float hv = p[(size_t)i * DM];
            Sre = fmaf(pre, hv, Sre);
            Sim = fmaf(pim, hv, Sim);
            const float nre = pre * are - pim * aim;
            const float nim = pre * aim + pim * are;
            pre = nre; pim = nim;
        }
        g_Sre[b * DM + d] = Sre;
        g_Sim[b * DM + d] = Sim;
    }
}

// ---------------------------------------------------------------------------
// Kernel 4: y[l] = h[l] + Re(Dc)*prefix(h)[l]  (+ tail term on last chunk):
//   + Re( BC * A^{L-1-l} * S )   for l in [L-256, L-1]
// grid = (NCH, BSZ), 512 threads (one per channel d).
// ---------------------------------------------------------------------------
__global__ __launch_bounds__(512)
void pass2_kernel(float* __restrict__ Y,
                  const float* __restrict__ Are, const float* __restrict__ Aim,
                  const float* __restrict__ Bre, const float* __restrict__ Bim,
                  const float* __restrict__ Cre, const float* __restrict__ Cim,
                  const float* __restrict__ Dre)
{
    const int d = threadIdx.x;
    const int c = blockIdx.x;
    const int b = blockIdx.y;

    float off = 0.0f;
    for (int cc = 0; cc < c; ++cc) off += g_csum[(b * NCH + cc) * DM + d];

    const size_t base = ((size_t)b * LSEQ + (size_t)c * CHUNK) * DM + d;
    const float dre = Dre[d];
    float run = off;
    for (int i = 0; i < CHUNK; ++i) {
        const float hv = g_h[base + (size_t)i * DM];
        run += hv;
        Y[base + (size_t)i * DM] = fmaf(dre, run, hv);
    }

    if (c == NCH - 1) {
        const float are = Are[d], aim = Aim[d];
        const float bre = Bre[d], bim = Bim[d];
        const float cre = Cre[d], cim = Cim[d];
        const float bcre = bre * cre - bim * cim;
        const float bcim = bre * cim + bim * cre;
        const float Sre = g_Sre[b * DM + d];
        const float Sim = g_Sim[b * DM + d];
        float qre = 1.0f, qim = 0.0f;            // A^(L-1-l), starting at l=L-1
        for (int i = CHUNK - 1; i >= 0; --i) {
            const size_t idx = base + (size_t)i * DM;
            const float zre = qre * Sre - qim * Sim;
            const float zim = qre * Sim + qim * Sre;
            Y[idx] += bcre * zre - bcim * zim;
            const float nre = qre * are - qim * aim;
            const float nim = qre * aim + qim * are;
            qre = nre; qim = nim;
        }
    }
}

// ---------------------------------------------------------------------------
extern "C" void kernel_launch(void* const* d_in, const int* in_sizes, int n_in,
                              void* d_out, int out_size)
{
    const float* x    = (const float*)d_in[0];
    const float* Are  = (const float*)d_in[1];
    const float* Aim  = (const float*)d_in[2];
    const float* Bre  = (const float*)d_in[3];
    const float* Bim  = (const float*)d_in[4];
    const float* Cre  = (const float*)d_in[5];
    const float* Cim  = (const float*)d_in[6];
    const float* Dre  = (const float*)d_in[7];
    // d_in[8] = D_im (unused: only Re(Dc) survives)
    const float* W    = (const float*)d_in[9];
    const float* bias = (const float*)d_in[10];
    const float* gamma= (const float*)d_in[11];
    const float* beta = (const float*)d_in[12];
    float* out = (float*)d_out;

    gemm_bias_kernel<<<dim3(DM / 128, MTOT / 128), 256>>>(x, W, bias);
    ln_kernel<<<MTOT / 8, 256>>>(gamma, beta);
    pass1_kernel<<<dim3(NCH, BSZ), DM>>>(Are, Aim);
    pass2_kernel<<<dim3(NCH, BSZ), DM>>>(out, Are, Aim, Bre, Bim, Cre, Cim, Dre);
}

// round 4
// speedup vs baseline: 1.7231x; 1.7231x over previous
#include <cuda_runtime.h>
#include <cuda_bf16.h>
#include <cstdint>

#define DM   512
#define LSEQ 2048
#define BSZ  8
#define MTOT (BSZ * LSEQ)      /* 16384 rows */
#define NCH  8
#define CHUNK (LSEQ / NCH)     /* 256 */

// Scratch (allocation-free: __device__ globals)
__device__ float g_h[(size_t)MTOT * DM];            // 33.5 MB
__device__ float g_csum[BSZ * NCH * DM];
__device__ float g_Sre[BSZ * DM];
__device__ float g_Sim[BSZ * DM];

// ===========================================================================
// PTX helpers (arch-portable: sm_80+ tensor-core path, no 'a' features)
// ===========================================================================
static __device__ __forceinline__ uint32_t smem_u32(const void* p) {
    uint32_t a;
    asm("{ .reg .u64 t; cvta.to.shared.u64 t, %1; cvt.u32.u64 %0, t; }"
        : "=r"(a) : "l"(p));
    return a;
}

static __device__ __forceinline__ void ldsm_x4(uint32_t* r, uint32_t addr) {
    asm volatile("ldmatrix.sync.aligned.m8n8.x4.shared.b16 {%0,%1,%2,%3}, [%4];"
                 : "=r"(r[0]), "=r"(r[1]), "=r"(r[2]), "=r"(r[3]) : "r"(addr));
}

static __device__ __forceinline__ void mma_bf16(float* c, const uint32_t* a,
                                                const uint32_t* b) {
    asm volatile(
        "mma.sync.aligned.m16n8k16.row.col.f32.bf16.bf16.f32 "
        "{%0,%1,%2,%3},{%4,%5,%6,%7},{%8,%9},{%0,%1,%2,%3};"
        : "+f"(c[0]), "+f"(c[1]), "+f"(c[2]), "+f"(c[3])
        : "r"(a[0]), "r"(a[1]), "r"(a[2]), "r"(a[3]), "r"(b[0]), "r"(b[1]));
}

static __device__ __forceinline__ uint32_t pack_bf2(__nv_bfloat16 a, __nv_bfloat16 b) {
    return ((uint32_t)__bfloat16_as_ushort(b) << 16) | __bfloat16_as_ushort(a);
}

// split one float4 into hi (bf16 rn) and lo (residual as bf16)
static __device__ __forceinline__ void split4(float4 v, uint2& hi, uint2& lo) {
    const __nv_bfloat16 hx = __float2bfloat16_rn(v.x);
    const __nv_bfloat16 hy = __float2bfloat16_rn(v.y);
    const __nv_bfloat16 hz = __float2bfloat16_rn(v.z);
    const __nv_bfloat16 hw = __float2bfloat16_rn(v.w);
    hi.x = pack_bf2(hx, hy);
    hi.y = pack_bf2(hz, hw);
    const __nv_bfloat16 lx = __float2bfloat16_rn(v.x - __bfloat162float(hx));
    const __nv_bfloat16 ly = __float2bfloat16_rn(v.y - __bfloat162float(hy));
    const __nv_bfloat16 lz = __float2bfloat16_rn(v.z - __bfloat162float(hz));
    const __nv_bfloat16 lw = __float2bfloat16_rn(v.w - __bfloat162float(hw));
    lo.x = pack_bf2(lx, ly);
    lo.y = pack_bf2(lz, lw);
}

// ===========================================================================
// Kernel 1: split-bf16 mma.sync GEMM. H[m][n] = sum_k X[m][k]W[n][k] + bias[n]
// CTA tile 128x128, K-chunks of 32, double-buffered SMEM, 8 warps (64x32 each)
// h = x_hi*W_hi + x_hi*W_lo + x_lo*W_hi   (fp32 accumulate)
// ===========================================================================
#define KC       32
#define NKC      (DM / KC)                 /* 16 chunks */
#define TSTRIDE  40                        /* bf16 elems per smem row (80 B) */
#define TILE_B   (128 * TSTRIDE * 2)       /* 10240 B per tile */
#define BUF_B    (4 * TILE_B)              /* A_hi, A_lo, B_hi, B_lo = 40960 */
#define SMEM_B   (2 * BUF_B)               /* 81920 B */

// tile order within a buffer: A_hi(+0), A_lo(+10240), B_hi(+20480), B_lo(+30720)
static __device__ __forceinline__ void conv_store(char* smem, uint32_t bufoff,
                                                  const float4* xa, const float4* wb,
                                                  const int* rows, const int* c4s)
{
#pragma unroll
    for (int j = 0; j < 4; ++j) {
        const uint32_t off = bufoff + (uint32_t)(rows[j] * 80 + c4s[j] * 8);
        uint2 hi, lo;
        split4(xa[j], hi, lo);
        *(uint2*)(smem + off)              = hi;
        *(uint2*)(smem + off + TILE_B)     = lo;
        split4(wb[j], hi, lo);
        *(uint2*)(smem + off + 2 * TILE_B) = hi;
        *(uint2*)(smem + off + 3 * TILE_B) = lo;
    }
}

__global__ __launch_bounds__(256, 1)
void gemm_mma_kernel(const float* __restrict__ X, const float* __restrict__ W,
                     const float* __restrict__ bias)
{
    extern __shared__ char smem[];
    const uint32_t sb = smem_u32(smem);
    const int tid  = threadIdx.x;
    const int wid  = tid >> 5;
    const int lane = tid & 31;
    const int bm   = blockIdx.y * 128;
    const int bn   = blockIdx.x * 128;
    const int wm   = (wid & 1) * 64;      // warp m-offset in CTA tile
    const int wn   = (wid >> 1) * 32;     // warp n-offset

    int rows[4], c4s[4];
#pragma unroll
    for (int j = 0; j < 4; ++j) {
        const int p = tid + j * 256;
        rows[j] = p >> 3;                 // 0..127
        c4s[j]  = p & 7;                  // float4 index within 32-col row
    }

    float acc[4][4][4];
#pragma unroll
    for (int mt = 0; mt < 4; ++mt)
#pragma unroll
        for (int nt = 0; nt < 4; ++nt)
#pragma unroll
            for (int q = 0; q < 4; ++q) acc[mt][nt][q] = 0.0f;

    const float* Xb = X + (size_t)bm * DM;
    const float* Wb = W + (size_t)bn * DM;

    // prologue: chunk 0 -> buffer 0
    float4 xa[4], wb4[4];
#pragma unroll
    for (int j = 0; j < 4; ++j) {
        xa[j]  = *(const float4*)(Xb + (size_t)rows[j] * DM + c4s[j] * 4);
        wb4[j] = *(const float4*)(Wb + (size_t)rows[j] * DM + c4s[j] * 4);
    }
    conv_store(smem, 0, xa, wb4, rows, c4s);
    __syncthreads();

    // ldmatrix lane-address components
    const int a_lr  = lane & 15;                 // A row within 16-row tile
    const int a_lk  = (lane >> 4) * 8;           // A k-half
    const int b_nr  = ((lane >> 4) & 1) * 8 + (lane & 7);  // B n within 16-row pair
    const int b_lk  = ((lane >> 3) & 1) * 8;     // B k-half

    int buf = 0;
    for (int kc = 0; kc < NKC; ++kc) {
        if (kc + 1 < NKC) {
#pragma unroll
            for (int j = 0; j < 4; ++j) {
                xa[j]  = *(const float4*)(Xb + (size_t)rows[j] * DM + (kc + 1) * KC + c4s[j] * 4);
                wb4[j] = *(const float4*)(Wb + (size_t)rows[j] * DM + (kc + 1) * KC + c4s[j] * 4);
            }
        }
        const uint32_t sA = sb + buf * BUF_B;
        const uint32_t sB = sA + 2 * TILE_B;

#pragma unroll
        for (int ks = 0; ks < 2; ++ks) {
            uint32_t ah[4][4], al[4][4], bh[4][2], bl[4][2];
#pragma unroll
            for (int mt = 0; mt < 4; ++mt) {
                const uint32_t aaddr = sA +
                    (uint32_t)((wm + mt * 16 + a_lr) * 80 + (ks * 16 + a_lk) * 2);
                ldsm_x4(ah[mt], aaddr);
                ldsm_x4(al[mt], aaddr + TILE_B);
            }
#pragma unroll
            for (int np = 0; np < 2; ++np) {
                const uint32_t baddr = sB +
                    (uint32_t)((wn + np * 16 + b_nr) * 80 + (ks * 16 + b_lk) * 2);
                uint32_t t[4];
                ldsm_x4(t, baddr);
                bh[np * 2][0] = t[0]; bh[np * 2][1] = t[1];
                bh[np * 2 + 1][0] = t[2]; bh[np * 2 + 1][1] = t[3];
                ldsm_x4(t, baddr + TILE_B);
                bl[np * 2][0] = t[0]; bl[np * 2][1] = t[1];
                bl[np * 2 + 1][0] = t[2]; bl[np * 2 + 1][1] = t[3];
            }
#pragma unroll
            for (int mt = 0; mt < 4; ++mt)
#pragma unroll
                for (int nt = 0; nt < 4; ++nt) {
                    mma_bf16(acc[mt][nt], ah[mt], bh[nt]);
                    mma_bf16(acc[mt][nt], ah[mt], bl[nt]);
                    mma_bf16(acc[mt][nt], al[mt], bh[nt]);
                }
        }

        if (kc + 1 < NKC) {
            conv_store(smem, (buf ^ 1) * BUF_B, xa, wb4, rows, c4s);
            __syncthreads();
            buf ^= 1;
        }
    }

    // epilogue: +bias, direct global stores (float2 per fragment half)
    const int gq = lane >> 2;          // row within 8
    const int r2 = (lane & 3) * 2;     // col pair
    float2 bv[4];
#pragma unroll
    for (int nt = 0; nt < 4; ++nt)
        bv[nt] = *(const float2*)(bias + bn + wn + nt * 8 + r2);
#pragma unroll
    for (int mt = 0; mt < 4; ++mt) {
        const int row0 = bm + wm + mt * 16 + gq;
#pragma unroll
        for (int nt = 0; nt < 4; ++nt) {
            const int col = bn + wn + nt * 8 + r2;
            float2 v0, v1;
            v0.x = acc[mt][nt][0] + bv[nt].x;
            v0.y = acc[mt][nt][1] + bv[nt].y;
            v1.x = acc[mt][nt][2] + bv[nt].x;
            v1.y = acc[mt][nt][3] + bv[nt].y;
            *(float2*)(g_h + (size_t)row0 * DM + col)       = v0;
            *(float2*)(g_h + (size_t)(row0 + 8) * DM + col) = v1;
        }
    }
}

// ---------------------------------------------------------------------------
// Kernel 2: LayerNorm over the feature dim, in place on g_h. (unchanged)
// ---------------------------------------------------------------------------
__global__ __launch_bounds__(256)
void ln_kernel(const float* __restrict__ gamma, const float* __restrict__ beta)
{
    const int warp = threadIdx.x >> 5;
    const int lane = threadIdx.x & 31;
    const int row  = blockIdx.x * 8 + warp;

    float* p = g_h + (size_t)row * DM;
    float4 v[4];
    float s = 0.0f, s2 = 0.0f;
#pragma unroll
    for (int i = 0; i < 4; ++i) {
        v[i] = *(const float4*)(p + lane * 4 + i * 128);
        s  += v[i].x + v[i].y + v[i].z + v[i].w;
        s2 += v[i].x * v[i].x + v[i].y * v[i].y + v[i].z * v[i].z + v[i].w * v[i].w;
    }
#pragma unroll
    for (int o = 16; o > 0; o >>= 1) {
        s  += __shfl_xor_sync(0xFFFFFFFFu, s,  o);
        s2 += __shfl_xor_sync(0xFFFFFFFFu, s2, o);
    }
    const float mu   = s * (1.0f / DM);
    const float var  = s2 * (1.0f / DM) - mu * mu;
    const float rstd = rsqrtf(var + 1e-5f);
#pragma unroll
    for (int i = 0; i < 4; ++i) {
        const int c0 = lane * 4 + i * 128;
        float4 g = *(const float4*)(gamma + c0);
        float4 bt = *(const float4*)(beta + c0);
        float4 o;
        o.x = (v[i].x - mu) * rstd * g.x + bt.x;
        o.y = (v[i].y - mu) * rstd * g.y + bt.y;
        o.z = (v[i].z - mu) * rstd * g.z + bt.z;
        o.w = (v[i].w - mu) * rstd * g.w + bt.w;
        *(float4*)(p + c0) = o;
    }
}

// ---------------------------------------------------------------------------
// Kernel 3: per-chunk sums + windowed complex S (chunk 0). (unchanged)
// ---------------------------------------------------------------------------
__global__ __launch_bounds__(512)
void pass1_kernel(const float* __restrict__ Are, const float* __restrict__ Aim)
{
    const int d = threadIdx.x;
    const int c = blockIdx.x;
    const int b = blockIdx.y;
    const float* p = g_h + ((size_t)b * LSEQ + (size_t)c * CHUNK) * DM + d;

    float s0 = 0.f, s1 = 0.f, s2 = 0.f, s3 = 0.f;
#pragma unroll 4
    for (int i = 0; i < CHUNK; i += 4) {
        s0 += p[(size_t)(i + 0) * DM];
        s1 += p[(size_t)(i + 1) * DM];
        s2 += p[(size_t)(i + 2) * DM];
        s3 += p[(size_t)(i + 3) * DM];
    }
    g_csum[(b * NCH + c) * DM + d] = (s0 + s1) + (s2 + s3);

    if (c == 0) {
        const float are = Are[d], aim = Aim[d];
        float pre = 1.0f, pim = 0.0f, Sre = 0.0f, Sim = 0.0f;
        for (int i = 0; i < CHUNK; ++i) {
            const float hv = p[(size_t)i * DM];
            Sre = fmaf(pre, hv, Sre);
            Sim = fmaf(pim, hv, Sim);
            const float nre = pre * are - pim * aim;
            const float nim = pre * aim + pim * are;
            pre = nre; pim = nim;
        }
        g_Sre[b * DM + d] = Sre;
        g_Sim[b * DM + d] = Sim;
    }
}

// ---------------------------------------------------------------------------
// Kernel 4: prefix + residual + tail term. (unchanged)
// ---------------------------------------------------------------------------
__global__ __launch_bounds__(512)
void pass2_kernel(float* __restrict__ Y,
                  const float* __restrict__ Are, const float* __restrict__ Aim,
                  const float* __restrict__ Bre, const float* __restrict__ Bim,
                  const float* __restrict__ Cre, const float* __restrict__ Cim,
                  const float* __restrict__ Dre)
{
    const int d = threadIdx.x;
    const int c = blockIdx.x;
    const int b = blockIdx.y;

    float off = 0.0f;
    for (int cc = 0; cc < c; ++cc) off += g_csum[(b * NCH + cc) * DM + d];

    const size_t base = ((size_t)b * LSEQ + (size_t)c * CHUNK) * DM + d;
    const float dre = Dre[d];
    float run = off;
    for (int i = 0; i < CHUNK; ++i) {
        const float hv = g_h[base + (size_t)i * DM];
        run += hv;
        Y[base + (size_t)i * DM] = fmaf(dre, run, hv);
    }

    if (c == NCH - 1) {
        const float are = Are[d], aim = Aim[d];
        const float bre = Bre[d], bim = Bim[d];
        const float cre = Cre[d], cim = Cim[d];
        const float bcre = bre * cre - bim * cim;
        const float bcim = bre * cim + bim * cre;
        const float Sre = g_Sre[b * DM + d];
        const float Sim = g_Sim[b * DM + d];
        float qre = 1.0f, qim = 0.0f;
        for (int i = CHUNK - 1; i >= 0; --i) {
            const size_t idx = base + (size_t)i * DM;
            const float zre = qre * Sre - qim * Sim;
            const float zim = qre * Sim + qim * Sre;
            Y[idx] += bcre * zre - bcim * zim;
            const float nre = qre * are - qim * aim;
            const float nim = qre * aim + qim * are;
            qre = nre; qim = nim;
        }
    }
}

// ---------------------------------------------------------------------------
extern "C" void kernel_launch(void* const* d_in, const int* in_sizes, int n_in,
                              void* d_out, int out_size)
{
    const float* x    = (const float*)d_in[0];
    const float* Are  = (const float*)d_in[1];
    const float* Aim  = (const float*)d_in[2];
    const float* Bre  = (const float*)d_in[3];
    const float* Bim  = (const float*)d_in[4];
    const float* Cre  = (const float*)d_in[5];
    const float* Cim  = (const float*)d_in[6];
    const float* Dre  = (const float*)d_in[7];
    const float* W    = (const float*)d_in[9];
    const float* bias = (const float*)d_in[10];
    const float* gamma= (const float*)d_in[11];
    const float* beta = (const float*)d_in[12];
    float* out = (float*)d_out;

    cudaFuncSetAttribute(gemm_mma_kernel,
                         cudaFuncAttributeMaxDynamicSharedMemorySize, SMEM_B);
    gemm_mma_kernel<<<dim3(DM / 128, MTOT / 128), 256, SMEM_B>>>(x, W, bias);
    ln_kernel<<<MTOT / 8, 256>>>(gamma, beta);
    pass1_kernel<<<dim3(NCH, BSZ), DM>>>(Are, Aim);
    pass2_kernel<<<dim3(NCH, BSZ), DM>>>(out, Are, Aim, Bre, Bim, Cre, Cim, Dre);
}

// round 5
// speedup vs baseline: 2.3305x; 1.3525x over previous
#include <cuda_runtime.h>
#include <cuda_fp16.h>
#include <cstdint>

#define DM   512
#define LSEQ 2048
#define BSZ  8
#define MTOT (BSZ * LSEQ)      /* 16384 rows */
#define NCH  32
#define CHUNK (LSEQ / NCH)     /* 64 */
#define NSP  4                 /* S partial chunks (t < 256) */

// Scratch (allocation-free: __device__ globals)
__device__ float g_h[(size_t)MTOT * DM];            // 33.5 MB
__device__ float g_csum[BSZ * NCH * DM];
__device__ float g_Sre[BSZ * NSP * DM];
__device__ float g_Sim[BSZ * NSP * DM];

// ===========================================================================
// PTX helpers (arch-portable: sm_80+ tensor-core path, no 'a' features)
// ===========================================================================
static __device__ __forceinline__ uint32_t smem_u32(const void* p) {
    uint32_t a;
    asm("{ .reg .u64 t; cvta.to.shared.u64 t, %1; cvt.u32.u64 %0, t; }"
        : "=r"(a) : "l"(p));
    return a;
}

static __device__ __forceinline__ void ldsm_x4(uint32_t* r, uint32_t addr) {
    asm volatile("ldmatrix.sync.aligned.m8n8.x4.shared.b16 {%0,%1,%2,%3}, [%4];"
                 : "=r"(r[0]), "=r"(r[1]), "=r"(r[2]), "=r"(r[3]) : "r"(addr));
}

static __device__ __forceinline__ void mma_f16(float* c, const uint32_t* a,
                                               const uint32_t* b) {
    asm volatile(
        "mma.sync.aligned.m16n8k16.row.col.f32.f16.f16.f32 "
        "{%0,%1,%2,%3},{%4,%5,%6,%7},{%8,%9},{%0,%1,%2,%3};"
        : "+f"(c[0]), "+f"(c[1]), "+f"(c[2]), "+f"(c[3])
        : "r"(a[0]), "r"(a[1]), "r"(a[2]), "r"(a[3]), "r"(b[0]), "r"(b[1]));
}

static __device__ __forceinline__ uint32_t pack_h2(__half a, __half b) {
    return ((uint32_t)__half_as_ushort(b) << 16) | __half_as_ushort(a);
}

// split one float4 into hi (fp16 rn) and lo (residual as fp16): ~22-bit x
static __device__ __forceinline__ void split4h(float4 v, uint2& hi, uint2& lo) {
    const __half hx = __float2half_rn(v.x);
    const __half hy = __float2half_rn(v.y);
    const __half hz = __float2half_rn(v.z);
    const __half hw = __float2half_rn(v.w);
    hi.x = pack_h2(hx, hy);
    hi.y = pack_h2(hz, hw);
    const __half lx = __float2half_rn(v.x - __half2float(hx));
    const __half ly = __float2half_rn(v.y - __half2float(hy));
    const __half lz = __float2half_rn(v.z - __half2float(hz));
    const __half lw = __float2half_rn(v.w - __half2float(hw));
    lo.x = pack_h2(lx, ly);
    lo.y = pack_h2(lz, lw);
}
static __device__ __forceinline__ uint2 cvt4h(float4 v) {
    uint2 r;
    r.x = pack_h2(__float2half_rn(v.x), __float2half_rn(v.y));
    r.y = pack_h2(__float2half_rn(v.z), __float2half_rn(v.w));
    return r;
}

// ===========================================================================
// Kernel 1: fp16 x-split mma.sync GEMM. H = X W^T + bias
// CTA 128x128, K-chunks of 32, double-buffered. h = x_hi*W + x_lo*W (2 MMAs)
// ===========================================================================
#define KC       32
#define NKC      (DM / KC)                 /* 16 chunks */
#define TSTRIDE  40                        /* halfs per smem row (80 B) */
#define TILE_B   (128 * TSTRIDE * 2)       /* 10240 B per tile */
#define BUF_B    (3 * TILE_B)              /* A_hi, A_lo, B = 30720 */
#define SMEM_B   (2 * BUF_B)               /* 61440 B */

static __device__ __forceinline__ void conv_store(char* smem, uint32_t bufoff,
                                                  const float4* xa, const float4* wb,
                                                  const int* rows, const int* c4s)
{
#pragma unroll
    for (int j = 0; j < 4; ++j) {
        const uint32_t off = bufoff + (uint32_t)(rows[j] * 80 + c4s[j] * 8);
        uint2 hi, lo;
        split4h(xa[j], hi, lo);
        *(uint2*)(smem + off)              = hi;
        *(uint2*)(smem + off + TILE_B)     = lo;
        *(uint2*)(smem + off + 2 * TILE_B) = cvt4h(wb[j]);
    }
}

__global__ __launch_bounds__(256, 1)
void gemm_mma_kernel(const float* __restrict__ X, const float* __restrict__ W,
                     const float* __restrict__ bias)
{
    extern __shared__ char smem[];
    const uint32_t sb = smem_u32(smem);
    const int tid  = threadIdx.x;
    const int wid  = tid >> 5;
    const int lane = tid & 31;
    const int bm   = blockIdx.y * 128;
    const int bn   = blockIdx.x * 128;
    const int wm   = (wid & 1) * 64;
    const int wn   = (wid >> 1) * 32;

    int rows[4], c4s[4];
#pragma unroll
    for (int j = 0; j < 4; ++j) {
        const int p = tid + j * 256;
        rows[j] = p >> 3;
        c4s[j]  = p & 7;
    }

    float acc[4][4][4];
#pragma unroll
    for (int mt = 0; mt < 4; ++mt)
#pragma unroll
        for (int nt = 0; nt < 4; ++nt)
#pragma unroll
            for (int q = 0; q < 4; ++q) acc[mt][nt][q] = 0.0f;

    const float* Xb = X + (size_t)bm * DM;
    const float* Wb = W + (size_t)bn * DM;

    float4 xa[4], wb4[4];
#pragma unroll
    for (int j = 0; j < 4; ++j) {
        xa[j]  = *(const float4*)(Xb + (size_t)rows[j] * DM + c4s[j] * 4);
        wb4[j] = *(const float4*)(Wb + (size_t)rows[j] * DM + c4s[j] * 4);
    }
    conv_store(smem, 0, xa, wb4, rows, c4s);
    __syncthreads();

    const int a_lr  = lane & 15;
    const int a_lk  = (lane >> 4) * 8;
    const int b_nr  = ((lane >> 4) & 1) * 8 + (lane & 7);
    const int b_lk  = ((lane >> 3) & 1) * 8;

    int buf = 0;
    for (int kc = 0; kc < NKC; ++kc) {
        if (kc + 1 < NKC) {
#pragma unroll
            for (int j = 0; j < 4; ++j) {
                xa[j]  = *(const float4*)(Xb + (size_t)rows[j] * DM + (kc + 1) * KC + c4s[j] * 4);
                wb4[j] = *(const float4*)(Wb + (size_t)rows[j] * DM + (kc + 1) * KC + c4s[j] * 4);
            }
        }
        const uint32_t sA = sb + buf * BUF_B;
        const uint32_t sB = sA + 2 * TILE_B;

#pragma unroll
        for (int ks = 0; ks < 2; ++ks) {
            uint32_t ah[4][4], al[4][4], bf[4][2];
#pragma unroll
            for (int mt = 0; mt < 4; ++mt) {
                const uint32_t aaddr = sA +
                    (uint32_t)((wm + mt * 16 + a_lr) * 80 + (ks * 16 + a_lk) * 2);
                ldsm_x4(ah[mt], aaddr);
                ldsm_x4(al[mt], aaddr + TILE_B);
            }
#pragma unroll
            for (int np = 0; np < 2; ++np) {
                const uint32_t baddr = sB +
                    (uint32_t)((wn + np * 16 + b_nr) * 80 + (ks * 16 + b_lk) * 2);
                uint32_t t[4];
                ldsm_x4(t, baddr);
                bf[np * 2][0] = t[0]; bf[np * 2][1] = t[1];
                bf[np * 2 + 1][0] = t[2]; bf[np * 2 + 1][1] = t[3];
            }
#pragma unroll
            for (int mt = 0; mt < 4; ++mt)
#pragma unroll
                for (int nt = 0; nt < 4; ++nt) {
                    mma_f16(acc[mt][nt], ah[mt], bf[nt]);
                    mma_f16(acc[mt][nt], al[mt], bf[nt]);
                }
        }

        if (kc + 1 < NKC) {
            conv_store(smem, (buf ^ 1) * BUF_B, xa, wb4, rows, c4s);
            __syncthreads();
            buf ^= 1;
        }
    }

    const int gq = lane >> 2;
    const int r2 = (lane & 3) * 2;
    float2 bv[4];
#pragma unroll
    for (int nt = 0; nt < 4; ++nt)
        bv[nt] = *(const float2*)(bias + bn + wn + nt * 8 + r2);
#pragma unroll
    for (int mt = 0; mt < 4; ++mt) {
        const int row0 = bm + wm + mt * 16 + gq;
#pragma unroll
        for (int nt = 0; nt < 4; ++nt) {
            const int col = bn + wn + nt * 8 + r2;
            float2 v0, v1;
            v0.x = acc[mt][nt][0] + bv[nt].x;
            v0.y = acc[mt][nt][1] + bv[nt].y;
            v1.x = acc[mt][nt][2] + bv[nt].x;
            v1.y = acc[mt][nt][3] + bv[nt].y;
            *(float2*)(g_h + (size_t)row0 * DM + col)       = v0;
            *(float2*)(g_h + (size_t)(row0 + 8) * DM + col) = v1;
        }
    }
}

// ---------------------------------------------------------------------------
// Kernel 2: LayerNorm over the feature dim, in place on g_h.
// ---------------------------------------------------------------------------
__global__ __launch_bounds__(256)
void ln_kernel(const float* __restrict__ gamma, const float* __restrict__ beta)
{
    const int warp = threadIdx.x >> 5;
    const int lane = threadIdx.x & 31;
    const int row  = blockIdx.x * 8 + warp;

    float* p = g_h + (size_t)row * DM;
    float4 v[4];
    float s = 0.0f, s2 = 0.0f;
#pragma unroll
    for (int i = 0; i < 4; ++i) {
        v[i] = *(const float4*)(p + lane * 4 + i * 128);
        s  += v[i].x + v[i].y + v[i].z + v[i].w;
        s2 += v[i].x * v[i].x + v[i].y * v[i].y + v[i].z * v[i].z + v[i].w * v[i].w;
    }
#pragma unroll
    for (int o = 16; o > 0; o >>= 1) {
        s  += __shfl_xor_sync(0xFFFFFFFFu, s,  o);
        s2 += __shfl_xor_sync(0xFFFFFFFFu, s2, o);
    }
    const float mu   = s * (1.0f / DM);
    const float var  = s2 * (1.0f / DM) - mu * mu;
    const float rstd = rsqrtf(var + 1e-5f);
#pragma unroll
    for (int i = 0; i < 4; ++i) {
        const int c0 = lane * 4 + i * 128;
        float4 g = *(const float4*)(gamma + c0);
        float4 bt = *(const float4*)(beta + c0);
        float4 o;
        o.x = (v[i].x - mu) * rstd * g.x + bt.x;
        o.y = (v[i].y - mu) * rstd * g.y + bt.y;
        o.z = (v[i].z - mu) * rstd * g.z + bt.z;
        o.w = (v[i].w - mu) * rstd * g.w + bt.w;
        *(float4*)(p + c0) = o;
    }
}

// ---------------------------------------------------------------------------
// Kernel 3: per-chunk sums; chunks c<4 also emit pre-rotated partials of
// S = sum_{t<256} A^t h[t]:  Spart_c = A^(64c) * sum_{i<64} A^i h[64c+i]
// grid = (NCH=32, BSZ), 512 threads.
// ---------------------------------------------------------------------------
__global__ __launch_bounds__(512)
void pass1_kernel(const float* __restrict__ Are, const float* __restrict__ Aim)
{
    const int d = threadIdx.x;
    const int c = blockIdx.x;
    const int b = blockIdx.y;
    const float* p = g_h + ((size_t)b * LSEQ + (size_t)c * CHUNK) * DM + d;

    if (c < NSP) {
        const float are = Are[d], aim = Aim[d];
        float s = 0.0f;
        float pre = 1.0f, pim = 0.0f, Sre = 0.0f, Sim = 0.0f;
        for (int i = 0; i < CHUNK; ++i) {
            const float hv = p[(size_t)i * DM];
            s += hv;
            Sre = fmaf(pre, hv, Sre);
            Sim = fmaf(pim, hv, Sim);
            const float nre = pre * are - pim * aim;
            const float nim = pre * aim + pim * are;
            pre = nre; pim = nim;
        }
        g_csum[(b * NCH + c) * DM + d] = s;
        // rotate partial by A^(64c): 6 complex squarings -> A^64, then ^c
        float wre = 1.0f, wim = 0.0f;
        if (c > 0) {
            float tre = are, tim = aim;
#pragma unroll
            for (int k = 0; k < 6; ++k) {
                const float nr = tre * tre - tim * tim;
                const float ni = 2.0f * tre * tim;
                tre = nr; tim = ni;
            }
            for (int j = 0; j < c; ++j) {
                const float nr = wre * tre - wim * tim;
                const float ni = wre * tim + wim * tre;
                wre = nr; wim = ni;
            }
        }
        g_Sre[(b * NSP + c) * DM + d] = Sre * wre - Sim * wim;
        g_Sim[(b * NSP + c) * DM + d] = Sre * wim + Sim * wre;
    } else {
        float s0 = 0.f, s1 = 0.f, s2 = 0.f, s3 = 0.f;
#pragma unroll 4
        for (int i = 0; i < CHUNK; i += 4) {
            s0 += p[(size_t)(i + 0) * DM];
            s1 += p[(size_t)(i + 1) * DM];
            s2 += p[(size_t)(i + 2) * DM];
            s3 += p[(size_t)(i + 3) * DM];
        }
        g_csum[(b * NCH + c) * DM + d] = (s0 + s1) + (s2 + s3);
    }
}

// ---------------------------------------------------------------------------
// Kernel 4: y[l] = h[l] + ReDc*prefix(h)[l]; last chunk adds
// Re(BC * A^(L-1-l) * S).  grid = (NCH=32, BSZ), 512 threads.
// ---------------------------------------------------------------------------
__global__ __launch_bounds__(512)
void pass2_kernel(float* __restrict__ Y,
                  const float* __restrict__ Are, const float* __restrict__ Aim,
                  const float* __restrict__ Bre, const float* __restrict__ Bim,
                  const float* __restrict__ Cre, const float* __restrict__ Cim,
                  const float* __restrict__ Dre)
{
    const int d = threadIdx.x;
    const int c = blockIdx.x;
    const int b = blockIdx.y;

    const float* cs = g_csum + (size_t)b * NCH * DM + d;
    float off = 0.0f;
    for (int cc = 0; cc < c; ++cc) off += cs[(size_t)cc * DM];

    const size_t base = ((size_t)b * LSEQ + (size_t)c * CHUNK) * DM + d;
    const float dre = Dre[d];
    float run = off;
    for (int i = 0; i < CHUNK; ++i) {
        const float hv = g_h[base + (size_t)i * DM];
        run += hv;
        Y[base + (size_t)i * DM] = fmaf(dre, run, hv);
    }

    if (c == NCH - 1) {
        const float are = Are[d], aim = Aim[d];
        const float bre = Bre[d], bim = Bim[d];
        const float cre = Cre[d], cim = Cim[d];
        const float bcre = bre * cre - bim * cim;
        const float bcim = bre * cim + bim * cre;
        float Sre = 0.0f, Sim = 0.0f;
#pragma unroll
        for (int j = 0; j < NSP; ++j) {
            Sre += g_Sre[(b * NSP + j) * DM + d];
            Sim += g_Sim[(b * NSP + j) * DM + d];
        }
        float qre = 1.0f, qim = 0.0f;       // A^(L-1-l), starting at l = L-1
        for (int i = CHUNK - 1; i >= 0; --i) {
            const size_t idx = base + (size_t)i * DM;
            const float zre = qre * Sre - qim * Sim;
            const float zim = qre * Sim + qim * Sre;
            Y[idx] += bcre * zre - bcim * zim;
            const float nre = qre * are - qim * aim;
            const float nim = qre * aim + qim * are;
            qre = nre; qim = nim;
        }
    }
}

// ---------------------------------------------------------------------------
extern "C" void kernel_launch(void* const* d_in, const int* in_sizes, int n_in,
                              void* d_out, int out_size)
{
    const float* x    = (const float*)d_in[0];
    const float* Are  = (const float*)d_in[1];
    const float* Aim  = (const float*)d_in[2];
    const float* Bre  = (const float*)d_in[3];
    const float* Bim  = (const float*)d_in[4];
    const float* Cre  = (const float*)d_in[5];
    const float* Cim  = (const float*)d_in[6];
    const float* Dre  = (const float*)d_in[7];
    const float* W    = (const float*)d_in[9];
    const float* bias = (const float*)d_in[10];
    const float* gamma= (const float*)d_in[11];
    const float* beta = (const float*)d_in[12];
    float* out = (float*)d_out;

    cudaFuncSetAttribute(gemm_mma_kernel,
                         cudaFuncAttributeMaxDynamicSharedMemorySize, SMEM_B);
    gemm_mma_kernel<<<dim3(DM / 128, MTOT / 128), 256, SMEM_B>>>(x, W, bias);
    ln_kernel<<<MTOT / 8, 256>>>(gamma, beta);
    pass1_kernel<<<dim3(NCH, BSZ), DM>>>(Are, Aim);
    pass2_kernel<<<dim3(NCH, BSZ), DM>>>(out, Are, Aim, Bre, Bim, Cre, Cim, Dre);
}

// round 6
// speedup vs baseline: 2.5128x; 1.0782x over previous
#include <cuda_runtime.h>
#include <cuda_fp16.h>
#include <cstdint>

#define DM   512
#define LSEQ 2048
#define BSZ  8
#define MTOT (BSZ * LSEQ)      /* 16384 rows */
#define NCH  32
#define CHUNK (LSEQ / NCH)     /* 64 */
#define NSP  4                 /* S partial chunks (t < 256) */

// Scratch (allocation-free: __device__ globals)
__device__ float g_h[(size_t)MTOT * DM];            // 33.5 MB (raw GEMM output)
__device__ float g_mu[MTOT];
__device__ float g_rs[MTOT];
__device__ float g_csum[BSZ * NCH * DM];
__device__ float g_Sre[BSZ * NSP * DM];
__device__ float g_Sim[BSZ * NSP * DM];

// ===========================================================================
// PTX helpers (arch-portable: sm_80+ tensor-core path, no 'a' features)
// ===========================================================================
static __device__ __forceinline__ uint32_t smem_u32(const void* p) {
    uint32_t a;
    asm("{ .reg .u64 t; cvta.to.shared.u64 t, %1; cvt.u32.u64 %0, t; }"
        : "=r"(a) : "l"(p));
    return a;
}

static __device__ __forceinline__ void ldsm_x4(uint32_t* r, uint32_t addr) {
    asm volatile("ldmatrix.sync.aligned.m8n8.x4.shared.b16 {%0,%1,%2,%3}, [%4];"
                 : "=r"(r[0]), "=r"(r[1]), "=r"(r[2]), "=r"(r[3]) : "r"(addr));
}

static __device__ __forceinline__ void mma_f16(float* c, const uint32_t* a,
                                               const uint32_t* b) {
    asm volatile(
        "mma.sync.aligned.m16n8k16.row.col.f32.f16.f16.f32 "
        "{%0,%1,%2,%3},{%4,%5,%6,%7},{%8,%9},{%0,%1,%2,%3};"
        : "+f"(c[0]), "+f"(c[1]), "+f"(c[2]), "+f"(c[3])
        : "r"(a[0]), "r"(a[1]), "r"(a[2]), "r"(a[3]), "r"(b[0]), "r"(b[1]));
}

static __device__ __forceinline__ uint32_t pack_h2(__half a, __half b) {
    return ((uint32_t)__half_as_ushort(b) << 16) | __half_as_ushort(a);
}
static __device__ __forceinline__ uint2 cvt4h(float4 v) {
    uint2 r;
    r.x = pack_h2(__float2half_rn(v.x), __float2half_rn(v.y));
    r.y = pack_h2(__float2half_rn(v.z), __float2half_rn(v.w));
    return r;
}

// ===========================================================================
// Kernel 1: fp16 mma.sync GEMM. H = X W^T + bias (single MMA per k-tile)
// CTA 128x128, K-chunks of 32, double-buffered SMEM, 8 warps (64x32 each)
// ===========================================================================
#define KC       32
#define NKC      (DM / KC)                 /* 16 chunks */
#define TSTRIDE  40                        /* halfs per smem row (80 B) */
#define TILE_B   (128 * TSTRIDE * 2)       /* 10240 B per tile */
#define BUF_B    (2 * TILE_B)              /* A, B = 20480 */
#define SMEM_B   (2 * BUF_B)               /* 40960 B */

static __device__ __forceinline__ void conv_store(char* smem, uint32_t bufoff,
                                                  const float4* xa, const float4* wb,
                                                  const int* rows, const int* c4s)
{
#pragma unroll
    for (int j = 0; j < 4; ++j) {
        const uint32_t off = bufoff + (uint32_t)(rows[j] * 80 + c4s[j] * 8);
        *(uint2*)(smem + off)          = cvt4h(xa[j]);
        *(uint2*)(smem + off + TILE_B) = cvt4h(wb[j]);
    }
}

__global__ __launch_bounds__(256, 1)
void gemm_mma_kernel(const float* __restrict__ X, const float* __restrict__ W,
                     const float* __restrict__ bias)
{
    extern __shared__ char smem[];
    const uint32_t sb = smem_u32(smem);
    const int tid  = threadIdx.x;
    const int wid  = tid >> 5;
    const int lane = tid & 31;
    const int bm   = blockIdx.y * 128;
    const int bn   = blockIdx.x * 128;
    const int wm   = (wid & 1) * 64;
    const int wn   = (wid >> 1) * 32;

    int rows[4], c4s[4];
#pragma unroll
    for (int j = 0; j < 4; ++j) {
        const int p = tid + j * 256;
        rows[j] = p >> 3;
        c4s[j]  = p & 7;
    }

    float acc[4][4][4];
#pragma unroll
    for (int mt = 0; mt < 4; ++mt)
#pragma unroll
        for (int nt = 0; nt < 4; ++nt)
#pragma unroll
            for (int q = 0; q < 4; ++q) acc[mt][nt][q] = 0.0f;

    const float* Xb = X + (size_t)bm * DM;
    const float* Wb = W + (size_t)bn * DM;

    float4 xa[4], wb4[4];
#pragma unroll
    for (int j = 0; j < 4; ++j) {
        xa[j]  = *(const float4*)(Xb + (size_t)rows[j] * DM + c4s[j] * 4);
        wb4[j] = *(const float4*)(Wb + (size_t)rows[j] * DM + c4s[j] * 4);
    }
    conv_store(smem, 0, xa, wb4, rows, c4s);
    __syncthreads();

    const int a_lr  = lane & 15;
    const int a_lk  = (lane >> 4) * 8;
    const int b_nr  = ((lane >> 4) & 1) * 8 + (lane & 7);
    const int b_lk  = ((lane >> 3) & 1) * 8;

    int buf = 0;
    for (int kc = 0; kc < NKC; ++kc) {
        if (kc + 1 < NKC) {
#pragma unroll
            for (int j = 0; j < 4; ++j) {
                xa[j]  = *(const float4*)(Xb + (size_t)rows[j] * DM + (kc + 1) * KC + c4s[j] * 4);
                wb4[j] = *(const float4*)(Wb + (size_t)rows[j] * DM + (kc + 1) * KC + c4s[j] * 4);
            }
        }
        const uint32_t sA = sb + buf * BUF_B;
        const uint32_t sB = sA + TILE_B;

#pragma unroll
        for (int ks = 0; ks < 2; ++ks) {
            uint32_t ah[4][4], bf[4][2];
#pragma unroll
            for (int mt = 0; mt < 4; ++mt) {
                const uint32_t aaddr = sA +
                    (uint32_t)((wm + mt * 16 + a_lr) * 80 + (ks * 16 + a_lk) * 2);
                ldsm_x4(ah[mt], aaddr);
            }
#pragma unroll
            for (int np = 0; np < 2; ++np) {
                const uint32_t baddr = sB +
                    (uint32_t)((wn + np * 16 + b_nr) * 80 + (ks * 16 + b_lk) * 2);
                uint32_t t[4];
                ldsm_x4(t, baddr);
                bf[np * 2][0] = t[0]; bf[np * 2][1] = t[1];
                bf[np * 2 + 1][0] = t[2]; bf[np * 2 + 1][1] = t[3];
            }
#pragma unroll
            for (int mt = 0; mt < 4; ++mt)
#pragma unroll
                for (int nt = 0; nt < 4; ++nt)
                    mma_f16(acc[mt][nt], ah[mt], bf[nt]);
        }

        if (kc + 1 < NKC) {
            conv_store(smem, (buf ^ 1) * BUF_B, xa, wb4, rows, c4s);
            __syncthreads();
            buf ^= 1;
        }
    }

    const int gq = lane >> 2;
    const int r2 = (lane & 3) * 2;
    float2 bv[4];
#pragma unroll
    for (int nt = 0; nt < 4; ++nt)
        bv[nt] = *(const float2*)(bias + bn + wn + nt * 8 + r2);
#pragma unroll
    for (int mt = 0; mt < 4; ++mt) {
        const int row0 = bm + wm + mt * 16 + gq;
#pragma unroll
        for (int nt = 0; nt < 4; ++nt) {
            const int col = bn + wn + nt * 8 + r2;
            float2 v0, v1;
            v0.x = acc[mt][nt][0] + bv[nt].x;
            v0.y = acc[mt][nt][1] + bv[nt].y;
            v1.x = acc[mt][nt][2] + bv[nt].x;
            v1.y = acc[mt][nt][3] + bv[nt].y;
            *(float2*)(g_h + (size_t)row0 * DM + col)       = v0;
            *(float2*)(g_h + (size_t)(row0 + 8) * DM + col) = v1;
        }
    }
}

// ===========================================================================
// Kernel 2 (fused): per-row LN stats + chunk sums of normalized h + windowed
// complex S partials (chunks c < NSP). Normalization applied on the fly;
// stats written to g_mu / g_rs for pass2. grid = (NCH, BSZ), 512 threads.
// ===========================================================================
__global__ __launch_bounds__(512)
void stat_pass1_kernel(const float* __restrict__ Are, const float* __restrict__ Aim,
                       const float* __restrict__ gamma, const float* __restrict__ beta)
{
    __shared__ float s_mu[CHUNK], s_rs[CHUNK];
    const int tid  = threadIdx.x;
    const int warp = tid >> 5;
    const int lane = tid & 31;
    const int c = blockIdx.x;
    const int b = blockIdx.y;
    const size_t row0 = (size_t)b * LSEQ + (size_t)c * CHUNK;

    // phase 1: 16 warps x 4 rows -> mu/rstd per row
#pragma unroll
    for (int j = 0; j < 4; ++j) {
        const int i = warp * 4 + j;
        const float* p = g_h + (row0 + i) * DM;
        float s = 0.0f, s2 = 0.0f;
#pragma unroll
        for (int q = 0; q < 4; ++q) {
            const float4 v = *(const float4*)(p + lane * 4 + q * 128);
            s  += v.x + v.y + v.z + v.w;
            s2 += v.x * v.x + v.y * v.y + v.z * v.z + v.w * v.w;
        }
#pragma unroll
        for (int o = 16; o > 0; o >>= 1) {
            s  += __shfl_xor_sync(0xFFFFFFFFu, s,  o);
            s2 += __shfl_xor_sync(0xFFFFFFFFu, s2, o);
        }
        if (lane == 0) {
            const float mu   = s * (1.0f / DM);
            const float var  = s2 * (1.0f / DM) - mu * mu;
            const float rstd = rsqrtf(var + 1e-5f);
            s_mu[i] = mu;  s_rs[i] = rstd;
            g_mu[row0 + i] = mu;  g_rs[row0 + i] = rstd;
        }
    }
    __syncthreads();

    // phase 2: thread per channel d, normalize on the fly (chunk is L2-hot)
    const int d = tid;
    const float gd = gamma[d], bd = beta[d];
    const float* p = g_h + row0 * DM + d;

    if (c < NSP) {
        const float are = Are[d], aim = Aim[d];
        float s = 0.0f;
        float pre = 1.0f, pim = 0.0f, Sre = 0.0f, Sim = 0.0f;
        for (int i = 0; i < CHUNK; ++i) {
            const float hn = (p[(size_t)i * DM] - s_mu[i]) * s_rs[i] * gd + bd;
            s += hn;
            Sre = fmaf(pre, hn, Sre);
            Sim = fmaf(pim, hn, Sim);
            const float nre = pre * are - pim * aim;
            const float nim = pre * aim + pim * are;
            pre = nre; pim = nim;
        }
        g_csum[(b * NCH + c) * DM + d] = s;
        // rotate partial by A^(64c): 6 complex squarings -> A^64, then ^c
        float wre = 1.0f, wim = 0.0f;
        if (c > 0) {
            float tre = are, tim = aim;
#pragma unroll
            for (int k = 0; k < 6; ++k) {
                const float nr = tre * tre - tim * tim;
                const float ni = 2.0f * tre * tim;
                tre = nr; tim = ni;
            }
            for (int j = 0; j < c; ++j) {
                const float nr = wre * tre - wim * tim;
                const float ni = wre * tim + wim * tre;
                wre = nr; wim = ni;
            }
        }
        g_Sre[(b * NSP + c) * DM + d] = Sre * wre - Sim * wim;
        g_Sim[(b * NSP + c) * DM + d] = Sre * wim + Sim * wre;
    } else {
        float s0 = 0.f, s1 = 0.f;
#pragma unroll 2
        for (int i = 0; i < CHUNK; i += 2) {
            s0 += (p[(size_t)(i + 0) * DM] - s_mu[i + 0]) * s_rs[i + 0];
            s1 += (p[(size_t)(i + 1) * DM] - s_mu[i + 1]) * s_rs[i + 1];
        }
        // sum of (raw-mu)*rstd*gd + bd  =  gd * sum((raw-mu)*rstd) + 64*bd
        g_csum[(b * NCH + c) * DM + d] = fmaf(gd, s0 + s1, (float)CHUNK * bd);
    }
}

// ===========================================================================
// Kernel 3: y[l] = hn[l] + ReDc*prefix(hn)[l]; last chunk adds
// Re(BC * A^(L-1-l) * S).  Normalization on the fly from g_h + stats.
// grid = (NCH, BSZ), 512 threads.
// ===========================================================================
__global__ __launch_bounds__(512)
void pass2_kernel(float* __restrict__ Y,
                  const float* __restrict__ Are, const float* __restrict__ Aim,
                  const float* __restrict__ Bre, const float* __restrict__ Bim,
                  const float* __restrict__ Cre, const float* __restrict__ Cim,
                  const float* __restrict__ Dre,
                  const float* __restrict__ gamma, const float* __restrict__ beta)
{
    __shared__ float s_mu[CHUNK], s_rs[CHUNK];
    const int d = threadIdx.x;
    const int c = blockIdx.x;
    const int b = blockIdx.y;
    const size_t row0 = (size_t)b * LSEQ + (size_t)c * CHUNK;

    if (d < CHUNK) {
        s_mu[d] = g_mu[row0 + d];
        s_rs[d] = g_rs[row0 + d];
    }
    __syncthreads();

    const float* cs = g_csum + (size_t)b * NCH * DM + d;
    float off = 0.0f;
    for (int cc = 0; cc < c; ++cc) off += cs[(size_t)cc * DM];

    const size_t base = row0 * DM + d;
    const float gd = gamma[d], bd = beta[d];
    const float dre = Dre[d];
    float run = off;
    for (int i = 0; i < CHUNK; ++i) {
        const float hn = (g_h[base + (size_t)i * DM] - s_mu[i]) * s_rs[i] * gd + bd;
        run += hn;
        Y[base + (size_t)i * DM] = fmaf(dre, run, hn);
    }

    if (c == NCH - 1) {
        const float are = Are[d], aim = Aim[d];
        const float bre = Bre[d], bim = Bim[d];
        const float cre = Cre[d], cim = Cim[d];
        const float bcre = bre * cre - bim * cim;
        const float bcim = bre * cim + bim * cre;
        float Sre = 0.0f, Sim = 0.0f;
#pragma unroll
        for (int j = 0; j < NSP; ++j) {
            Sre += g_Sre[(b * NSP + j) * DM + d];
            Sim += g_Sim[(b * NSP + j) * DM + d];
        }
        float qre = 1.0f, qim = 0.0f;       // A^(L-1-l), starting at l = L-1
        for (int i = CHUNK - 1; i >= 0; --i) {
            const size_t idx = base + (size_t)i * DM;
            const float zre = qre * Sre - qim * Sim;
            const float zim = qre * Sim + qim * Sre;
            Y[idx] += bcre * zre - bcim * zim;
            const float nre = qre * are - qim * aim;
            const float nim = qre * aim + qim * are;
            qre = nre; qim = nim;
        }
    }
}

// ---------------------------------------------------------------------------
extern "C" void kernel_launch(void* const* d_in, const int* in_sizes, int n_in,
                              void* d_out, int out_size)
{
    const float* x    = (const float*)d_in[0];
    const float* Are  = (const float*)d_in[1];
    const float* Aim  = (const float*)d_in[2];
    const float* Bre  = (const float*)d_in[3];
    const float* Bim  = (const float*)d_in[4];
    const float* Cre  = (const float*)d_in[5];
    const float* Cim  = (const float*)d_in[6];
    const float* Dre  = (const float*)d_in[7];
    const float* W    = (const float*)d_in[9];
    const float* bias = (const float*)d_in[10];
    const float* gamma= (const float*)d_in[11];
    const float* beta = (const float*)d_in[12];
    float* out = (float*)d_out;

    cudaFuncSetAttribute(gemm_mma_kernel,
                         cudaFuncAttributeMaxDynamicSharedMemorySize, SMEM_B);
    gemm_mma_kernel<<<dim3(DM / 128, MTOT / 128), 256, SMEM_B>>>(x, W, bias);
    stat_pass1_kernel<<<dim3(NCH, BSZ), DM>>>(Are, Aim, gamma, beta);
    pass2_kernel<<<dim3(NCH, BSZ), DM>>>(out, Are, Aim, Bre, Bim, Cre, Cim, Dre,
                                         gamma, beta);
}

// round 7
// speedup vs baseline: 2.7035x; 1.0759x over previous
#include <cuda_runtime.h>
#include <cuda_fp16.h>
#include <cstdint>

#define DM   512
#define LSEQ 2048
#define BSZ  8
#define MTOT (BSZ * LSEQ)      /* 16384 rows */
#define NCH  64
#define CHUNK (LSEQ / NCH)     /* 32 */
#define NSP  8                 /* S partial chunks (t < 256) */

// Scratch (allocation-free: __device__ globals)
__device__ float g_h[(size_t)MTOT * DM];            // 33.5 MB (raw GEMM output)
__device__ float g_mu[MTOT];
__device__ float g_rs[MTOT];
__device__ float g_csum[BSZ * NCH * DM];
__device__ float g_Sre[BSZ * NSP * DM];
__device__ float g_Sim[BSZ * NSP * DM];

// ===========================================================================
// PTX helpers (arch-portable: sm_80+ tensor-core path, no 'a' features)
// ===========================================================================
static __device__ __forceinline__ uint32_t smem_u32(const void* p) {
    uint32_t a;
    asm("{ .reg .u64 t; cvta.to.shared.u64 t, %1; cvt.u32.u64 %0, t; }"
        : "=r"(a) : "l"(p));
    return a;
}

static __device__ __forceinline__ void ldsm_x4(uint32_t* r, uint32_t addr) {
    asm volatile("ldmatrix.sync.aligned.m8n8.x4.shared.b16 {%0,%1,%2,%3}, [%4];"
                 : "=r"(r[0]), "=r"(r[1]), "=r"(r[2]), "=r"(r[3]) : "r"(addr));
}

static __device__ __forceinline__ void mma_f16(float* c, const uint32_t* a,
                                               const uint32_t* b) {
    asm volatile(
        "mma.sync.aligned.m16n8k16.row.col.f32.f16.f16.f32 "
        "{%0,%1,%2,%3},{%4,%5,%6,%7},{%8,%9},{%0,%1,%2,%3};"
        : "+f"(c[0]), "+f"(c[1]), "+f"(c[2]), "+f"(c[3])
        : "r"(a[0]), "r"(a[1]), "r"(a[2]), "r"(a[3]), "r"(b[0]), "r"(b[1]));
}

static __device__ __forceinline__ uint32_t pack_h2(__half a, __half b) {
    return ((uint32_t)__half_as_ushort(b) << 16) | __half_as_ushort(a);
}
static __device__ __forceinline__ uint2 cvt4h(float4 v) {
    uint2 r;
    r.x = pack_h2(__float2half_rn(v.x), __float2half_rn(v.y));
    r.y = pack_h2(__float2half_rn(v.z), __float2half_rn(v.w));
    return r;
}

// ===========================================================================
// Kernel 1: fp16 mma.sync GEMM. H = X W^T + bias
// CTA 128x128, 512 threads / 16 warps (warp tile 32x32), K-chunks of 32,
// double-buffered SMEM.
// ===========================================================================
#define KC       32
#define NKC      (DM / KC)                 /* 16 chunks */
#define TSTRIDE  40                        /* halfs per smem row (80 B) */
#define TILE_B   (128 * TSTRIDE * 2)       /* 10240 B per tile */
#define BUF_B    (2 * TILE_B)              /* A, B = 20480 */

__global__ __launch_bounds__(512, 1)
void gemm_mma_kernel(const float* __restrict__ X, const float* __restrict__ W,
                     const float* __restrict__ bias)
{
    __shared__ char smem[2 * BUF_B];       /* 40 KB static */
    const uint32_t sb = smem_u32(smem);
    const int tid  = threadIdx.x;
    const int wid  = tid >> 5;
    const int lane = tid & 31;
    const int bm   = blockIdx.y * 128;
    const int bn   = blockIdx.x * 128;
    const int wm   = (wid & 3) * 32;       // 4 m-strips
    const int wn   = (wid >> 2) * 32;      // 4 n-strips

    int rows[2], c4s[2];
#pragma unroll
    for (int j = 0; j < 2; ++j) {
        const int p = tid + j * 512;
        rows[j] = p >> 3;                  // 0..127
        c4s[j]  = p & 7;
    }

    float acc[2][4][4];
#pragma unroll
    for (int mt = 0; mt < 2; ++mt)
#pragma unroll
        for (int nt = 0; nt < 4; ++nt)
#pragma unroll
            for (int q = 0; q < 4; ++q) acc[mt][nt][q] = 0.0f;

    const float* Xb = X + (size_t)bm * DM;
    const float* Wb = W + (size_t)bn * DM;

    float4 xa[2], wb4[2];
#pragma unroll
    for (int j = 0; j < 2; ++j) {
        xa[j]  = *(const float4*)(Xb + (size_t)rows[j] * DM + c4s[j] * 4);
        wb4[j] = *(const float4*)(Wb + (size_t)rows[j] * DM + c4s[j] * 4);
    }
#pragma unroll
    for (int j = 0; j < 2; ++j) {
        const uint32_t off = (uint32_t)(rows[j] * 80 + c4s[j] * 8);
        *(uint2*)(smem + off)          = cvt4h(xa[j]);
        *(uint2*)(smem + off + TILE_B) = cvt4h(wb4[j]);
    }
    __syncthreads();

    const int a_lr  = lane & 15;
    const int a_lk  = (lane >> 4) * 8;
    const int b_nr  = ((lane >> 4) & 1) * 8 + (lane & 7);
    const int b_lk  = ((lane >> 3) & 1) * 8;

    int buf = 0;
    for (int kc = 0; kc < NKC; ++kc) {
        if (kc + 1 < NKC) {
#pragma unroll
            for (int j = 0; j < 2; ++j) {
                xa[j]  = *(const float4*)(Xb + (size_t)rows[j] * DM + (kc + 1) * KC + c4s[j] * 4);
                wb4[j] = *(const float4*)(Wb + (size_t)rows[j] * DM + (kc + 1) * KC + c4s[j] * 4);
            }
        }
        const uint32_t sA = sb + buf * BUF_B;
        const uint32_t sB = sA + TILE_B;

#pragma unroll
        for (int ks = 0; ks < 2; ++ks) {
            uint32_t ah[2][4], bf[4][2];
#pragma unroll
            for (int mt = 0; mt < 2; ++mt) {
                const uint32_t aaddr = sA +
                    (uint32_t)((wm + mt * 16 + a_lr) * 80 + (ks * 16 + a_lk) * 2);
                ldsm_x4(ah[mt], aaddr);
            }
#pragma unroll
            for (int np = 0; np < 2; ++np) {
                const uint32_t baddr = sB +
                    (uint32_t)((wn + np * 16 + b_nr) * 80 + (ks * 16 + b_lk) * 2);
                uint32_t t[4];
                ldsm_x4(t, baddr);
                bf[np * 2][0] = t[0]; bf[np * 2][1] = t[1];
                bf[np * 2 + 1][0] = t[2]; bf[np * 2 + 1][1] = t[3];
            }
#pragma unroll
            for (int mt = 0; mt < 2; ++mt)
#pragma unroll
                for (int nt = 0; nt < 4; ++nt)
                    mma_f16(acc[mt][nt], ah[mt], bf[nt]);
        }

        if (kc + 1 < NKC) {
            const uint32_t bo = (buf ^ 1) * BUF_B;
#pragma unroll
            for (int j = 0; j < 2; ++j) {
                const uint32_t off = bo + (uint32_t)(rows[j] * 80 + c4s[j] * 8);
                *(uint2*)(smem + off)          = cvt4h(xa[j]);
                *(uint2*)(smem + off + TILE_B) = cvt4h(wb4[j]);
            }
            __syncthreads();
            buf ^= 1;
        }
    }

    const int gq = lane >> 2;
    const int r2 = (lane & 3) * 2;
    float2 bv[4];
#pragma unroll
    for (int nt = 0; nt < 4; ++nt)
        bv[nt] = *(const float2*)(bias + bn + wn + nt * 8 + r2);
#pragma unroll
    for (int mt = 0; mt < 2; ++mt) {
        const int row0 = bm + wm + mt * 16 + gq;
#pragma unroll
        for (int nt = 0; nt < 4; ++nt) {
            const int col = bn + wn + nt * 8 + r2;
            float2 v0, v1;
            v0.x = acc[mt][nt][0] + bv[nt].x;
            v0.y = acc[mt][nt][1] + bv[nt].y;
            v1.x = acc[mt][nt][2] + bv[nt].x;
            v1.y = acc[mt][nt][3] + bv[nt].y;
            *(float2*)(g_h + (size_t)row0 * DM + col)       = v0;
            *(float2*)(g_h + (size_t)(row0 + 8) * DM + col) = v1;
        }
    }
}

// ===========================================================================
// Kernel 2 (fused): per-row LN stats + chunk sums of normalized h + windowed
// complex S partials (chunks c < NSP). grid = (NCH=64, BSZ), 512 threads.
// ===========================================================================
__global__ __launch_bounds__(512)
void stat_pass1_kernel(const float* __restrict__ Are, const float* __restrict__ Aim,
                       const float* __restrict__ gamma, const float* __restrict__ beta)
{
    __shared__ float s_mu[CHUNK], s_rs[CHUNK];
    const int tid  = threadIdx.x;
    const int warp = tid >> 5;
    const int lane = tid & 31;
    const int c = blockIdx.x;
    const int b = blockIdx.y;
    const size_t row0 = (size_t)b * LSEQ + (size_t)c * CHUNK;

    // phase 1: 16 warps x 2 rows -> mu/rstd per row
#pragma unroll
    for (int j = 0; j < 2; ++j) {
        const int i = warp * 2 + j;
        const float* p = g_h + (row0 + i) * DM;
        float s = 0.0f, s2 = 0.0f;
#pragma unroll
        for (int q = 0; q < 4; ++q) {
            const float4 v = *(const float4*)(p + lane * 4 + q * 128);
            s  += v.x + v.y + v.z + v.w;
            s2 += v.x * v.x + v.y * v.y + v.z * v.z + v.w * v.w;
        }
#pragma unroll
        for (int o = 16; o > 0; o >>= 1) {
            s  += __shfl_xor_sync(0xFFFFFFFFu, s,  o);
            s2 += __shfl_xor_sync(0xFFFFFFFFu, s2, o);
        }
        if (lane == 0) {
            const float mu   = s * (1.0f / DM);
            const float var  = s2 * (1.0f / DM) - mu * mu;
            const float rstd = rsqrtf(var + 1e-5f);
            s_mu[i] = mu;  s_rs[i] = rstd;
            g_mu[row0 + i] = mu;  g_rs[row0 + i] = rstd;
        }
    }
    __syncthreads();

    // phase 2: thread per channel d, normalize on the fly (chunk is L2-hot)
    const int d = tid;
    const float gd = gamma[d], bd = beta[d];
    const float* p = g_h + row0 * DM + d;

    if (c < NSP) {
        const float are = Are[d], aim = Aim[d];
        float s = 0.0f;
        float pre = 1.0f, pim = 0.0f, Sre = 0.0f, Sim = 0.0f;
        for (int i = 0; i < CHUNK; ++i) {
            const float hn = (p[(size_t)i * DM] - s_mu[i]) * s_rs[i] * gd + bd;
            s += hn;
            Sre = fmaf(pre, hn, Sre);
            Sim = fmaf(pim, hn, Sim);
            const float nre = pre * are - pim * aim;
            const float nim = pre * aim + pim * are;
            pre = nre; pim = nim;
        }
        g_csum[(b * NCH + c) * DM + d] = s;
        // rotate partial by A^(32c): 5 complex squarings -> A^32, then ^c
        float wre = 1.0f, wim = 0.0f;
        if (c > 0) {
            float tre = are, tim = aim;
#pragma unroll
            for (int k = 0; k < 5; ++k) {
                const float nr = tre * tre - tim * tim;
                const float ni = 2.0f * tre * tim;
                tre = nr; tim = ni;
            }
            for (int j = 0; j < c; ++j) {
                const float nr = wre * tre - wim * tim;
                const float ni = wre * tim + wim * tre;
                wre = nr; wim = ni;
            }
        }
        g_Sre[(b * NSP + c) * DM + d] = Sre * wre - Sim * wim;
        g_Sim[(b * NSP + c) * DM + d] = Sre * wim + Sim * wre;
    } else {
        float s0 = 0.f, s1 = 0.f;
#pragma unroll 2
        for (int i = 0; i < CHUNK; i += 2) {
            s0 += (p[(size_t)(i + 0) * DM] - s_mu[i + 0]) * s_rs[i + 0];
            s1 += (p[(size_t)(i + 1) * DM] - s_mu[i + 1]) * s_rs[i + 1];
        }
        g_csum[(b * NCH + c) * DM + d] = fmaf(gd, s0 + s1, (float)CHUNK * bd);
    }
}

// ===========================================================================
// Kernel 3: y[l] = hn[l] + ReDc*prefix(hn)[l]; last chunk adds
// Re(BC * A^(L-1-l) * S).  grid = (NCH=64, BSZ), 512 threads.
// ===========================================================================
__global__ __launch_bounds__(512)
void pass2_kernel(float* __restrict__ Y,
                  const float* __restrict__ Are, const float* __restrict__ Aim,
                  const float* __restrict__ Bre, const float* __restrict__ Bim,
                  const float* __restrict__ Cre, const float* __restrict__ Cim,
                  const float* __restrict__ Dre,
                  const float* __restrict__ gamma, const float* __restrict__ beta)
{
    __shared__ float s_mu[CHUNK], s_rs[CHUNK];
    const int d = threadIdx.x;
    const int c = blockIdx.x;
    const int b = blockIdx.y;
    const size_t row0 = (size_t)b * LSEQ + (size_t)c * CHUNK;

    if (d < CHUNK) {
        s_mu[d] = g_mu[row0 + d];
        s_rs[d] = g_rs[row0 + d];
    }
    __syncthreads();

    const float* cs = g_csum + (size_t)b * NCH * DM + d;
    float off = 0.0f;
    for (int cc = 0; cc < c; ++cc) off += cs[(size_t)cc * DM];

    const size_t base = row0 * DM + d;
    const float gd = gamma[d], bd = beta[d];
    const float dre = Dre[d];
    float run = off;
    for (int i = 0; i < CHUNK; ++i) {
        const float hn = (g_h[base + (size_t)i * DM] - s_mu[i]) * s_rs[i] * gd + bd;
        run += hn;
        Y[base + (size_t)i * DM] = fmaf(dre, run, hn);
    }

    if (c == NCH - 1) {
        const float are = Are[d], aim = Aim[d];
        const float bre = Bre[d], bim = Bim[d];
        const float cre = Cre[d], cim = Cim[d];
        const float bcre = bre * cre - bim * cim;
        const float bcim = bre * cim + bim * cre;
        float Sre = 0.0f, Sim = 0.0f;
#pragma unroll
        for (int j = 0; j < NSP; ++j) {
            Sre += g_Sre[(b * NSP + j) * DM + d];
            Sim += g_Sim[(b * NSP + j) * DM + d];
        }
        float qre = 1.0f, qim = 0.0f;       // A^(L-1-l), starting at l = L-1
        for (int i = CHUNK - 1; i >= 0; --i) {
            const size_t idx = base + (size_t)i * DM;
            const float zre = qre * Sre - qim * Sim;
            const float zim = qre * Sim + qim * Sre;
            Y[idx] += bcre * zre - bcim * zim;
            const float nre = qre * are - qim * aim;
            const float nim = qre * aim + qim * are;
            qre = nre; qim = nim;
        }
    }
}

// ---------------------------------------------------------------------------
extern "C" void kernel_launch(void* const* d_in, const int* in_sizes, int n_in,
                              void* d_out, int out_size)
{
    const float* x    = (const float*)d_in[0];
    const float* Are  = (const float*)d_in[1];
    const float* Aim  = (const float*)d_in[2];
    const float* Bre  = (const float*)d_in[3];
    const float* Bim  = (const float*)d_in[4];
    const float* Cre  = (const float*)d_in[5];
    const float* Cim  = (const float*)d_in[6];
    const float* Dre  = (const float*)d_in[7];
    const float* W    = (const float*)d_in[9];
    const float* bias = (const float*)d_in[10];
    const float* gamma= (const float*)d_in[11];
    const float* beta = (const float*)d_in[12];
    float* out = (float*)d_out;

    gemm_mma_kernel<<<dim3(DM / 128, MTOT / 128), 512>>>(x, W, bias);
    stat_pass1_kernel<<<dim3(NCH, BSZ), DM>>>(Are, Aim, gamma, beta);
    pass2_kernel<<<dim3(NCH, BSZ), DM>>>(out, Are, Aim, Bre, Bim, Cre, Cim, Dre,
                                         gamma, beta);
}